// round 10
// baseline (speedup 1.0000x reference)
#include <cuda_runtime.h>
#include <cuda_fp16.h>
#include <cstdint>

#define CC 64
#define MAXB 64

// ---------------- device scratch (no allocations allowed) ----------------
__device__ float g_sums[MAXB * CC];
__device__ __align__(16) float g_c[MAXB * CC];        // per-segment fused bias (BN folded)
__device__ __align__(16) uint32_t g_Wfrag[4096];      // B frags fp16: uint2 = {b0, b1} per (kt,n,lane)

__device__ __forceinline__ uint32_t smem_u32(const void* p) {
    uint32_t a;
    asm("{ .reg .u64 t; cvta.to.shared.u64 t, %1; cvt.u32.u64 %0, t; }" : "=r"(a) : "l"(p));
    return a;
}

// ---------------- pass 0: zero sums ----------------
__global__ void k_zero(int n) {
    int i = blockIdx.x * blockDim.x + threadIdx.x;
    if (i < n) g_sums[i] = 0.f;
}

// ---------------- pass 1: segment sums (float4, MLP=4, smem tree, few atomics) ----------------
__global__ void k_segsum(const float4* __restrict__ x4, const int* __restrict__ o,
                         int N, int Bseg) {
    __shared__ int so[MAXB];
    __shared__ float4 red[256];
    int t = threadIdx.x;
    if (t < Bseg) so[t] = o[t];
    __syncthreads();
    int c4 = t & 15, rg = t >> 4;
    int rpb = (N + gridDim.x - 1) / gridDim.x;
    int r0 = blockIdx.x * rpb;
    if (r0 >= N) return;
    int r1 = min(N, r0 + rpb);
    int s0 = 0; while (s0 < Bseg - 1 && r0 >= so[s0]) s0++;
    int s1 = s0; while (s1 < Bseg - 1 && (r1 - 1) >= so[s1]) s1++;
    if (s0 == s1) {
        float4 a0 = make_float4(0.f, 0.f, 0.f, 0.f);
        float4 a1 = make_float4(0.f, 0.f, 0.f, 0.f);
        float4 a2 = make_float4(0.f, 0.f, 0.f, 0.f);
        float4 a3 = make_float4(0.f, 0.f, 0.f, 0.f);
        int row = r0 + rg;
        for (; row + 48 < r1; row += 64) {
            float4 v0 = x4[(size_t)row * 16 + c4];
            float4 v1 = x4[(size_t)(row + 16) * 16 + c4];
            float4 v2 = x4[(size_t)(row + 32) * 16 + c4];
            float4 v3 = x4[(size_t)(row + 48) * 16 + c4];
            a0.x += v0.x; a0.y += v0.y; a0.z += v0.z; a0.w += v0.w;
            a1.x += v1.x; a1.y += v1.y; a1.z += v1.z; a1.w += v1.w;
            a2.x += v2.x; a2.y += v2.y; a2.z += v2.z; a2.w += v2.w;
            a3.x += v3.x; a3.y += v3.y; a3.z += v3.z; a3.w += v3.w;
        }
        for (; row < r1; row += 16) {
            float4 v = x4[(size_t)row * 16 + c4];
            a0.x += v.x; a0.y += v.y; a0.z += v.z; a0.w += v.w;
        }
        a0.x += a1.x + a2.x + a3.x; a0.y += a1.y + a2.y + a3.y;
        a0.z += a1.z + a2.z + a3.z; a0.w += a1.w + a2.w + a3.w;
        red[t] = a0;
        __syncthreads();
        #pragma unroll
        for (int s = 8; s >= 1; s >>= 1) {
            if (rg < s) {
                float4 b = red[t + 16 * s];
                float4 a = red[t];
                a.x += b.x; a.y += b.y; a.z += b.z; a.w += b.w;
                red[t] = a;
            }
            __syncthreads();
        }
        if (rg == 0) {
            float4 v = red[t];
            float* dst = &g_sums[s0 * CC + c4 * 4];
            atomicAdd(dst + 0, v.x); atomicAdd(dst + 1, v.y);
            atomicAdd(dst + 2, v.z); atomicAdd(dst + 3, v.w);
        }
    } else {
        int seg = s0;
        float4 a = make_float4(0.f, 0.f, 0.f, 0.f);
        for (int row = r0 + rg; row < r1; row += 16) {
            while (seg < Bseg - 1 && row >= so[seg]) {
                float* dst = &g_sums[seg * CC + c4 * 4];
                atomicAdd(dst + 0, a.x); atomicAdd(dst + 1, a.y);
                atomicAdd(dst + 2, a.z); atomicAdd(dst + 3, a.w);
                a = make_float4(0.f, 0.f, 0.f, 0.f);
                seg++;
            }
            float4 v = x4[(size_t)row * 16 + c4];
            a.x += v.x; a.y += v.y; a.z += v.z; a.w += v.w;
        }
        float* dst = &g_sums[seg * CC + c4 * 4];
        atomicAdd(dst + 0, a.x); atomicAdd(dst + 1, a.y);
        atomicAdd(dst + 2, a.z); atomicAdd(dst + 3, a.w);
    }
}

// ---------------- pass 2 (tiny): MLP on pooled means, fold BN, build B frag image ----------------
__global__ void k_prep(const int* __restrict__ o, const float* __restrict__ W2,
                       const float* __restrict__ b2, const float* __restrict__ W1,
                       const float* __restrict__ b1, const float* __restrict__ gam,
                       const float* __restrict__ bet, const float* __restrict__ rmean,
                       const float* __restrict__ rvar, int Bseg) {
    __shared__ float mean[MAXB * CC];
    __shared__ float h[MAXB * CC];
    __shared__ float ss[CC], st[CC];
    int tid = threadIdx.x;
    if (tid < CC) {
        float sv = gam[tid] * rsqrtf(rvar[tid] + 1e-5f);
        ss[tid] = sv;
        st[tid] = bet[tid] - rmean[tid] * sv;
    }
    for (int i = tid; i < Bseg * CC; i += blockDim.x) {
        int b = i >> 6;
        int cnt = o[b] - (b ? o[b - 1] : 0);
        mean[i] = g_sums[i] / (float)cnt;
    }
    __syncthreads();
    for (int i = tid; i < Bseg * CC; i += blockDim.x) {
        int b = i >> 6, j = i & 63;
        float acc = b2[j];
        #pragma unroll 8
        for (int k = 0; k < CC; k++) acc = fmaf(mean[b * CC + k], W2[k * CC + j], acc);
        h[i] = fmaxf(acc, 0.f);
    }
    __syncthreads();
    // per-segment fused bias: c = (h @ W1_bot + b1) * ss + st
    for (int i = tid; i < Bseg * CC; i += blockDim.x) {
        int b = i >> 6, j = i & 63;
        float acc = b1[j];
        #pragma unroll 8
        for (int k = 0; k < CC; k++) acc = fmaf(h[b * CC + k], W1[(CC + k) * CC + j], acc);
        g_c[i] = acc * ss[j] + st[j];
    }
    // B frag image (fp16, single term): word i = ((kt*8 + n)*32 + lane)*2 + bslot
    //   frag col f = lane>>2, column PERMUTED for stmatrix-natural staging:
    //     n_col = n*8 + (f>>1) + (f&1)*4
    //   k2 = kt*16 + (lane&3)*2 + bslot*8;  W'[k][n] = W1[k*CC+n]*ss[n]
    for (int i = tid; i < 2048; i += blockDim.x) {
        int bslot = i & 1;
        int lane = (i >> 1) & 31;
        int grp = i >> 6;
        int n = grp & 7;
        int kt = grp >> 3;
        int f = lane >> 2;
        int n_col = n * 8 + (f >> 1) + ((f & 1) << 2);
        int k2 = kt * 16 + (lane & 3) * 2 + bslot * 8;
        float sv = ss[n_col];
        float w0 = W1[k2 * CC + n_col] * sv;
        float w1 = W1[(k2 + 1) * CC + n_col] * sv;
        __half2 hp = __floats2half2_rn(w0, w1);
        g_Wfrag[i] = *reinterpret_cast<uint32_t*>(&hp);
    }
}

// ---------------- MMA / ldmatrix / stmatrix helpers ----------------
__device__ __forceinline__ void mma16816h(float* c, const uint4& a, uint32_t b0, uint32_t b1) {
    asm volatile(
        "mma.sync.aligned.m16n8k16.row.col.f32.f16.f16.f32 "
        "{%0,%1,%2,%3}, {%4,%5,%6,%7}, {%8,%9}, {%0,%1,%2,%3};"
        : "+f"(c[0]), "+f"(c[1]), "+f"(c[2]), "+f"(c[3])
        : "r"(a.x), "r"(a.y), "r"(a.z), "r"(a.w), "r"(b0), "r"(b1));
}
__device__ __forceinline__ uint4 ldsm_x4(uint32_t addr) {
    uint4 r;
    asm volatile("ldmatrix.sync.aligned.m8n8.x4.shared.b16 {%0,%1,%2,%3}, [%4];"
        : "=r"(r.x), "=r"(r.y), "=r"(r.z), "=r"(r.w) : "r"(addr));
    return r;
}
__device__ __forceinline__ void stsm_x4(uint32_t addr, uint32_t r0, uint32_t r1,
                                        uint32_t r2, uint32_t r3) {
    asm volatile("stmatrix.sync.aligned.m8n8.x4.shared.b16 [%0], {%1,%2,%3,%4};"
        :: "r"(addr), "r"(r0), "r"(r1), "r"(r2), "r"(r3) : "memory");
}

// ---------------- pass 3: out = relu(x @ W' + c[seg]) via fp16 2-term A split ----------------
// A panels: fp16[128 rows][64 k], 128 B/row, SW128 swizzle. hi at 0, lo at 16384.
// After the MMA loop, A region is reused as fp32 output stage: 128 rows x 256 B,
// 16B chunk at (row, c16) stored at byte row*256 + ((c16*16) ^ ((row&7)<<4)).
struct __align__(1024) SmemM {
    unsigned char A[32768];
    uint2 Bimg[1024];           // 8 KB: {b0, b1} fp16 pairs per (kt,n,lane)
    unsigned char segb[128];
};

__global__ __launch_bounds__(256)
void k_main(const float4* __restrict__ x4, const int* __restrict__ o,
            float* __restrict__ out, int N, int Bseg) {
    __shared__ SmemM sm;
    int tid = threadIdx.x;
    int base = blockIdx.x * 128;

    // copy B frag image (coalesced, 8 KB)
    {
        const uint4* src = reinterpret_cast<const uint4*>(g_Wfrag);
        uint4* dst = reinterpret_cast<uint4*>(sm.Bimg);
        #pragma unroll
        for (int j = 0; j < 2; j++) dst[tid + 256 * j] = src[tid + 256 * j];
    }
    // per-row segment ids
    if (tid < 128) {
        int row = min(base + tid, N - 1);
        int s = 0;
        while (s < Bseg - 1 && row >= __ldg(&o[s])) s++;
        sm.segb[tid] = (unsigned char)s;
    }

    // load x coalesced, convert hi/lo fp16, store row-major swizzled (2x STS.64/thread/iter)
    #pragma unroll
    for (int j = 0; j < 8; j++) {
        int idx = tid + 256 * j;
        int row = idx >> 4, c4 = idx & 15;
        int grow = base + row;
        float4 v = make_float4(0.f, 0.f, 0.f, 0.f);
        if (grow < N) v = x4[(size_t)grow * 16 + c4];

        __half2 h0 = __floats2half2_rn(v.x, v.y);
        __half2 h1 = __floats2half2_rn(v.z, v.w);
        float r0x = v.x - __low2float(h0);
        float r0y = v.y - __high2float(h0);
        float r1x = v.z - __low2float(h1);
        float r1y = v.w - __high2float(h1);
        __half2 l0 = __floats2half2_rn(r0x, r0y);
        __half2 l1 = __floats2half2_rn(r1x, r1y);

        uint32_t off = (uint32_t)(row * 128 + ((c4 * 8) ^ ((row & 7) << 4)));
        uint2 hw = make_uint2(*reinterpret_cast<uint32_t*>(&h0), *reinterpret_cast<uint32_t*>(&h1));
        uint2 lw = make_uint2(*reinterpret_cast<uint32_t*>(&l0), *reinterpret_cast<uint32_t*>(&l1));
        *reinterpret_cast<uint2*>(&sm.A[off])         = hw;
        *reinterpret_cast<uint2*>(&sm.A[off + 16384]) = lw;
    }
    __syncthreads();

    int lane = tid & 31, wid = tid >> 5;
    int wm = wid & 3;      // row group: rows wm*32 .. +31
    int wn = wid >> 2;     // col group: cols wn*32 .. +31

    int lm = lane >> 3, lr = lane & 7;
    uint32_t a_base = smem_u32(sm.A);
    uint32_t lane_row = (uint32_t)(wm * 32 + (lm & 1) * 8 + lr) * 128u;

    float acc[2][4][4];
    #pragma unroll
    for (int mb = 0; mb < 2; mb++)
        #pragma unroll
        for (int nt = 0; nt < 4; nt++)
            #pragma unroll
            for (int q = 0; q < 4; q++) acc[mb][nt][q] = 0.f;

    #pragma unroll
    for (int kt = 0; kt < 4; kt++) {
        uint32_t kcol = (uint32_t)((kt * 32 + (lm >> 1) * 16) ^ (lr << 4));
        uint4 ah[2], al[2];
        #pragma unroll
        for (int mb = 0; mb < 2; mb++) {
            uint32_t addr = a_base + lane_row + (uint32_t)(mb * 16 * 128) + kcol;
            ah[mb] = ldsm_x4(addr);
            al[mb] = ldsm_x4(addr + 16384);
        }
        #pragma unroll
        for (int nt = 0; nt < 4; nt++) {
            uint2 bv = sm.Bimg[(kt * 8 + wn * 4 + nt) * 32 + lane];
            #pragma unroll
            for (int mb = 0; mb < 2; mb++) {
                mma16816h(acc[mb][nt], ah[mb], bv.x, bv.y);   // hi * W
                mma16816h(acc[mb][nt], al[mb], bv.x, bv.y);   // lo * W
            }
        }
    }
    __syncthreads();   // all warps done reading A panels

    // stage accumulators via stmatrix.x4 (column-permuted B makes this row-natural)
    {
        int m = lane >> 3, rl8 = lane & 7;
        #pragma unroll
        for (int mb = 0; mb < 2; mb++) {
            int rrow = wm * 32 + mb * 16 + ((m & 1) << 3) + rl8;
            uint32_t rowb = a_base + (uint32_t)(rrow * 256);
            #pragma unroll
            for (int nt = 0; nt < 4; nt++) {
                int ci = wn * 8 + nt * 2 + (m >> 1);
                uint32_t addr = rowb + (uint32_t)((ci * 16) ^ (rl8 << 4));
                stsm_x4(addr,
                        __float_as_uint(acc[mb][nt][0]), __float_as_uint(acc[mb][nt][2]),
                        __float_as_uint(acc[mb][nt][1]), __float_as_uint(acc[mb][nt][3]));
            }
        }
    }
    __syncthreads();

    // read stage, add bias, relu, coalesced STG.128
    float4* out4 = reinterpret_cast<float4*>(out);
    #pragma unroll
    for (int j = 0; j < 8; j++) {
        int idx = tid + 256 * j;
        int row = idx >> 4, c4 = idx & 15;
        int grow = base + row;
        if (grow < N) {
            const float4 v = *reinterpret_cast<const float4*>(
                &sm.A[row * 256 + ((c4 * 16) ^ ((row & 7) << 4))]);
            int seg = sm.segb[row];
            float4 b = __ldg(reinterpret_cast<const float4*>(&g_c[seg * CC + c4 * 4]));
            float4 r;
            r.x = fmaxf(v.x + b.x, 0.f);
            r.y = fmaxf(v.y + b.y, 0.f);
            r.z = fmaxf(v.z + b.z, 0.f);
            r.w = fmaxf(v.w + b.w, 0.f);
            out4[(size_t)grow * 16 + c4] = r;
        }
    }
}

extern "C" void kernel_launch(void* const* d_in, const int* in_sizes, int n_in,
                              void* d_out, int out_size) {
    const float* x     = (const float*)d_in[0];
    const int*   o     = (const int*)  d_in[1];
    const float* W2    = (const float*)d_in[2];
    const float* b2    = (const float*)d_in[3];
    const float* W1    = (const float*)d_in[4];
    const float* b1    = (const float*)d_in[5];
    const float* gam   = (const float*)d_in[6];
    const float* bet   = (const float*)d_in[7];
    const float* rmean = (const float*)d_in[8];
    const float* rvar  = (const float*)d_in[9];
    float* out = (float*)d_out;

    int N = in_sizes[0] / CC;
    int B = in_sizes[1];

    k_zero<<<(B * CC + 255) / 256, 256>>>(B * CC);
    k_segsum<<<4096, 256>>>((const float4*)x, o, N, B);
    k_prep<<<1, 1024>>>(o, W2, b2, W1, b1, gam, bet, rmean, rvar, B);
    k_main<<<(N + 127) / 128, 256>>>((const float4*)x, o, out, N, B);
}

// round 11
// speedup vs baseline: 1.2957x; 1.2957x over previous
#include <cuda_runtime.h>
#include <cuda_fp16.h>
#include <cstdint>

#define CC 64
#define MAXB 64

// ---------------- device scratch (no allocations allowed) ----------------
__device__ float g_sums[MAXB * CC];                   // zeroed by k_prep after use (globals start zeroed)
__device__ __align__(16) float g_c[MAXB * CC];        // per-segment fused bias (BN folded)
__device__ __align__(16) uint32_t g_Wfrag[2048];      // B frags fp16: uint2 = {b0, b1} per (kt,n,lane)

__device__ __forceinline__ uint32_t smem_u32(const void* p) {
    uint32_t a;
    asm("{ .reg .u64 t; cvta.to.shared.u64 t, %1; cvt.u32.u64 %0, t; }" : "=r"(a) : "l"(p));
    return a;
}

// Veltkamp split at 13 bits: hi exactly fp16-representable, lo = exact residual.
__device__ __forceinline__ void vsplit(float v, float& hi, float& lo) {
    float t = __fmul_rn(v, 8193.0f);       // 2^13 + 1
    float d = __fsub_rn(t, v);
    hi = __fsub_rn(t, d);
    lo = __fsub_rn(v, hi);
}

// ---------------- pass 1: segment sums (float4, MLP=4, smem tree, few atomics) ----------------
__global__ void k_segsum(const float4* __restrict__ x4, const int* __restrict__ o,
                         int N, int Bseg) {
    __shared__ int so[MAXB];
    __shared__ float4 red[256];
    int t = threadIdx.x;
    if (t < Bseg) so[t] = o[t];
    __syncthreads();
    int c4 = t & 15, rg = t >> 4;
    int rpb = (N + gridDim.x - 1) / gridDim.x;
    int r0 = blockIdx.x * rpb;
    if (r0 >= N) return;
    int r1 = min(N, r0 + rpb);
    int s0 = 0; while (s0 < Bseg - 1 && r0 >= so[s0]) s0++;
    int s1 = s0; while (s1 < Bseg - 1 && (r1 - 1) >= so[s1]) s1++;
    if (s0 == s1) {
        float4 a0 = make_float4(0.f, 0.f, 0.f, 0.f);
        float4 a1 = make_float4(0.f, 0.f, 0.f, 0.f);
        float4 a2 = make_float4(0.f, 0.f, 0.f, 0.f);
        float4 a3 = make_float4(0.f, 0.f, 0.f, 0.f);
        int row = r0 + rg;
        for (; row + 48 < r1; row += 64) {
            float4 v0 = x4[(size_t)row * 16 + c4];
            float4 v1 = x4[(size_t)(row + 16) * 16 + c4];
            float4 v2 = x4[(size_t)(row + 32) * 16 + c4];
            float4 v3 = x4[(size_t)(row + 48) * 16 + c4];
            a0.x += v0.x; a0.y += v0.y; a0.z += v0.z; a0.w += v0.w;
            a1.x += v1.x; a1.y += v1.y; a1.z += v1.z; a1.w += v1.w;
            a2.x += v2.x; a2.y += v2.y; a2.z += v2.z; a2.w += v2.w;
            a3.x += v3.x; a3.y += v3.y; a3.z += v3.z; a3.w += v3.w;
        }
        for (; row < r1; row += 16) {
            float4 v = x4[(size_t)row * 16 + c4];
            a0.x += v.x; a0.y += v.y; a0.z += v.z; a0.w += v.w;
        }
        a0.x += a1.x + a2.x + a3.x; a0.y += a1.y + a2.y + a3.y;
        a0.z += a1.z + a2.z + a3.z; a0.w += a1.w + a2.w + a3.w;
        red[t] = a0;
        __syncthreads();
        #pragma unroll
        for (int s = 8; s >= 1; s >>= 1) {
            if (rg < s) {
                float4 b = red[t + 16 * s];
                float4 a = red[t];
                a.x += b.x; a.y += b.y; a.z += b.z; a.w += b.w;
                red[t] = a;
            }
            __syncthreads();
        }
        if (rg == 0) {
            float4 v = red[t];
            float* dst = &g_sums[s0 * CC + c4 * 4];
            atomicAdd(dst + 0, v.x); atomicAdd(dst + 1, v.y);
            atomicAdd(dst + 2, v.z); atomicAdd(dst + 3, v.w);
        }
    } else {
        int seg = s0;
        float4 a = make_float4(0.f, 0.f, 0.f, 0.f);
        for (int row = r0 + rg; row < r1; row += 16) {
            while (seg < Bseg - 1 && row >= so[seg]) {
                float* dst = &g_sums[seg * CC + c4 * 4];
                atomicAdd(dst + 0, a.x); atomicAdd(dst + 1, a.y);
                atomicAdd(dst + 2, a.z); atomicAdd(dst + 3, a.w);
                a = make_float4(0.f, 0.f, 0.f, 0.f);
                seg++;
            }
            float4 v = x4[(size_t)row * 16 + c4];
            a.x += v.x; a.y += v.y; a.z += v.z; a.w += v.w;
        }
        float* dst = &g_sums[seg * CC + c4 * 4];
        atomicAdd(dst + 0, a.x); atomicAdd(dst + 1, a.y);
        atomicAdd(dst + 2, a.z); atomicAdd(dst + 3, a.w);
    }
}

// ---------------- pass 2 (tiny): MLP on pooled means, fold BN, build B frag image ----------------
__global__ void k_prep(const int* __restrict__ o, const float* __restrict__ W2,
                       const float* __restrict__ b2, const float* __restrict__ W1,
                       const float* __restrict__ b1, const float* __restrict__ gam,
                       const float* __restrict__ bet, const float* __restrict__ rmean,
                       const float* __restrict__ rvar, int Bseg) {
    __shared__ float mean[MAXB * CC];
    __shared__ float h[MAXB * CC];
    __shared__ float ss[CC], st[CC];
    int tid = threadIdx.x;
    if (tid < CC) {
        float sv = gam[tid] * rsqrtf(rvar[tid] + 1e-5f);
        ss[tid] = sv;
        st[tid] = bet[tid] - rmean[tid] * sv;
    }
    for (int i = tid; i < Bseg * CC; i += blockDim.x) {
        int b = i >> 6;
        int cnt = o[b] - (b ? o[b - 1] : 0);
        mean[i] = g_sums[i] / (float)cnt;
        g_sums[i] = 0.f;                    // re-zero for next graph replay
    }
    __syncthreads();
    for (int i = tid; i < Bseg * CC; i += blockDim.x) {
        int b = i >> 6, j = i & 63;
        float acc = b2[j];
        #pragma unroll 8
        for (int k = 0; k < CC; k++) acc = fmaf(mean[b * CC + k], W2[k * CC + j], acc);
        h[i] = fmaxf(acc, 0.f);
    }
    __syncthreads();
    // per-segment fused bias: c = (h @ W1_bot + b1) * ss + st
    for (int i = tid; i < Bseg * CC; i += blockDim.x) {
        int b = i >> 6, j = i & 63;
        float acc = b1[j];
        #pragma unroll 8
        for (int k = 0; k < CC; k++) acc = fmaf(h[b * CC + k], W1[(CC + k) * CC + j], acc);
        g_c[i] = acc * ss[j] + st[j];
    }
    // B frag image (fp16, single term): word i = ((kt*8 + n)*32 + lane)*2 + bslot
    //   frag col f = lane>>2, column PERMUTED for stmatrix-natural staging:
    //     n_col = n*8 + (f>>1) + (f&1)*4
    //   k2 = kt*16 + (lane&3)*2 + bslot*8;  W'[k][n] = W1[k*CC+n]*ss[n]
    for (int i = tid; i < 2048; i += blockDim.x) {
        int bslot = i & 1;
        int lane = (i >> 1) & 31;
        int grp = i >> 6;
        int n = grp & 7;
        int kt = grp >> 3;
        int f = lane >> 2;
        int n_col = n * 8 + (f >> 1) + ((f & 1) << 2);
        int k2 = kt * 16 + (lane & 3) * 2 + bslot * 8;
        float sv = ss[n_col];
        float w0 = W1[k2 * CC + n_col] * sv;
        float w1 = W1[(k2 + 1) * CC + n_col] * sv;
        __half2 hp = __floats2half2_rn(w0, w1);
        g_Wfrag[i] = *reinterpret_cast<uint32_t*>(&hp);
    }
}

// ---------------- MMA / ldmatrix / stmatrix helpers ----------------
__device__ __forceinline__ void mma16816h(float* c, const uint4& a, uint32_t b0, uint32_t b1) {
    asm volatile(
        "mma.sync.aligned.m16n8k16.row.col.f32.f16.f16.f32 "
        "{%0,%1,%2,%3}, {%4,%5,%6,%7}, {%8,%9}, {%0,%1,%2,%3};"
        : "+f"(c[0]), "+f"(c[1]), "+f"(c[2]), "+f"(c[3])
        : "r"(a.x), "r"(a.y), "r"(a.z), "r"(a.w), "r"(b0), "r"(b1));
}
__device__ __forceinline__ uint4 ldsm_x4(uint32_t addr) {
    uint4 r;
    asm volatile("ldmatrix.sync.aligned.m8n8.x4.shared.b16 {%0,%1,%2,%3}, [%4];"
        : "=r"(r.x), "=r"(r.y), "=r"(r.z), "=r"(r.w) : "r"(addr));
    return r;
}
__device__ __forceinline__ void stsm_x4(uint32_t addr, uint32_t r0, uint32_t r1,
                                        uint32_t r2, uint32_t r3) {
    asm volatile("stmatrix.sync.aligned.m8n8.x4.shared.b16 [%0], {%1,%2,%3,%4};"
        :: "r"(addr), "r"(r0), "r"(r1), "r"(r2), "r"(r3) : "memory");
}

// ---------------- pass 3: out = relu(x @ W' + c[seg]) via fp16 2-term A split ----------------
// A panels: fp16[128 rows][64 k], 128 B/row, SW128 swizzle. hi at 0, lo at 16384.
// After the MMA loop, A region is reused as fp32 output stage: 128 rows x 256 B,
// 16B chunk at (row, c16) stored at byte row*256 + ((c16*16) ^ ((row&7)<<4)).
struct __align__(1024) SmemM {
    unsigned char A[32768];
    uint2 Bimg[1024];           // 8 KB: {b0, b1} fp16 pairs per (kt,n,lane)
    unsigned char segb[128];
};

__global__ __launch_bounds__(256)
void k_main(const float4* __restrict__ x4, const int* __restrict__ o,
            float* __restrict__ out, int N, int Bseg) {
    __shared__ SmemM sm;
    int tid = threadIdx.x;
    int base = blockIdx.x * 128;

    // copy B frag image (coalesced, 8 KB)
    {
        const uint4* src = reinterpret_cast<const uint4*>(g_Wfrag);
        uint4* dst = reinterpret_cast<uint4*>(sm.Bimg);
        #pragma unroll
        for (int j = 0; j < 2; j++) dst[tid + 256 * j] = src[tid + 256 * j];
    }
    // per-row segment ids
    if (tid < 128) {
        int row = min(base + tid, N - 1);
        int s = 0;
        while (s < Bseg - 1 && row >= __ldg(&o[s])) s++;
        sm.segb[tid] = (unsigned char)s;
    }

    // load x coalesced, Veltkamp hi/lo split (FFMA pipe only), pack fp16, STS.64 x2
    #pragma unroll
    for (int j = 0; j < 8; j++) {
        int idx = tid + 256 * j;
        int row = idx >> 4, c4 = idx & 15;
        int grow = base + row;
        float4 v = make_float4(0.f, 0.f, 0.f, 0.f);
        if (grow < N) v = x4[(size_t)grow * 16 + c4];

        float hx, lx, hy, ly, hz, lz, hw_, lw_;
        vsplit(v.x, hx, lx); vsplit(v.y, hy, ly);
        vsplit(v.z, hz, lz); vsplit(v.w, hw_, lw_);
        __half2 h0 = __floats2half2_rn(hx, hy);   // exact: hi has <=11-bit mantissa
        __half2 h1 = __floats2half2_rn(hz, hw_);
        __half2 l0 = __floats2half2_rn(lx, ly);
        __half2 l1 = __floats2half2_rn(lz, lw_);

        uint32_t off = (uint32_t)(row * 128 + ((c4 * 8) ^ ((row & 7) << 4)));
        uint2 hw2 = make_uint2(*reinterpret_cast<uint32_t*>(&h0), *reinterpret_cast<uint32_t*>(&h1));
        uint2 lw2 = make_uint2(*reinterpret_cast<uint32_t*>(&l0), *reinterpret_cast<uint32_t*>(&l1));
        *reinterpret_cast<uint2*>(&sm.A[off])         = hw2;
        *reinterpret_cast<uint2*>(&sm.A[off + 16384]) = lw2;
    }
    __syncthreads();

    int lane = tid & 31, wid = tid >> 5;
    int wm = wid & 3;      // row group: rows wm*32 .. +31
    int wn = wid >> 2;     // col group: cols wn*32 .. +31

    int lm = lane >> 3, lr = lane & 7;
    uint32_t a_base = smem_u32(sm.A);
    uint32_t lane_row = (uint32_t)(wm * 32 + (lm & 1) * 8 + lr) * 128u;

    float acc[2][4][4];
    #pragma unroll
    for (int mb = 0; mb < 2; mb++)
        #pragma unroll
        for (int nt = 0; nt < 4; nt++)
            #pragma unroll
            for (int q = 0; q < 4; q++) acc[mb][nt][q] = 0.f;

    #pragma unroll
    for (int kt = 0; kt < 4; kt++) {
        uint32_t kcol = (uint32_t)((kt * 32 + (lm >> 1) * 16) ^ (lr << 4));
        uint4 ah[2], al[2];
        #pragma unroll
        for (int mb = 0; mb < 2; mb++) {
            uint32_t addr = a_base + lane_row + (uint32_t)(mb * 16 * 128) + kcol;
            ah[mb] = ldsm_x4(addr);
            al[mb] = ldsm_x4(addr + 16384);
        }
        #pragma unroll
        for (int nt = 0; nt < 4; nt++) {
            uint2 bv = sm.Bimg[(kt * 8 + wn * 4 + nt) * 32 + lane];
            #pragma unroll
            for (int mb = 0; mb < 2; mb++) {
                mma16816h(acc[mb][nt], ah[mb], bv.x, bv.y);   // hi * W
                mma16816h(acc[mb][nt], al[mb], bv.x, bv.y);   // lo * W
            }
        }
    }
    __syncthreads();   // all warps done reading A panels

    // stage accumulators via stmatrix.x4 (column-permuted B makes this row-natural)
    {
        int m = lane >> 3, rl8 = lane & 7;
        #pragma unroll
        for (int mb = 0; mb < 2; mb++) {
            int rrow = wm * 32 + mb * 16 + ((m & 1) << 3) + rl8;
            uint32_t rowb = a_base + (uint32_t)(rrow * 256);
            #pragma unroll
            for (int nt = 0; nt < 4; nt++) {
                int ci = wn * 8 + nt * 2 + (m >> 1);
                uint32_t addr = rowb + (uint32_t)((ci * 16) ^ (rl8 << 4));
                stsm_x4(addr,
                        __float_as_uint(acc[mb][nt][0]), __float_as_uint(acc[mb][nt][2]),
                        __float_as_uint(acc[mb][nt][1]), __float_as_uint(acc[mb][nt][3]));
            }
        }
    }
    __syncthreads();

    // read stage, add bias, relu, coalesced STG.128
    float4* out4 = reinterpret_cast<float4*>(out);
    #pragma unroll
    for (int j = 0; j < 8; j++) {
        int idx = tid + 256 * j;
        int row = idx >> 4, c4 = idx & 15;
        int grow = base + row;
        if (grow < N) {
            const float4 v = *reinterpret_cast<const float4*>(
                &sm.A[row * 256 + ((c4 * 16) ^ ((row & 7) << 4))]);
            int seg = sm.segb[row];
            float4 b = __ldg(reinterpret_cast<const float4*>(&g_c[seg * CC + c4 * 4]));
            float4 r;
            r.x = fmaxf(v.x + b.x, 0.f);
            r.y = fmaxf(v.y + b.y, 0.f);
            r.z = fmaxf(v.z + b.z, 0.f);
            r.w = fmaxf(v.w + b.w, 0.f);
            out4[(size_t)grow * 16 + c4] = r;
        }
    }
}

extern "C" void kernel_launch(void* const* d_in, const int* in_sizes, int n_in,
                              void* d_out, int out_size) {
    const float* x     = (const float*)d_in[0];
    const int*   o     = (const int*)  d_in[1];
    const float* W2    = (const float*)d_in[2];
    const float* b2    = (const float*)d_in[3];
    const float* W1    = (const float*)d_in[4];
    const float* b1    = (const float*)d_in[5];
    const float* gam   = (const float*)d_in[6];
    const float* bet   = (const float*)d_in[7];
    const float* rmean = (const float*)d_in[8];
    const float* rvar  = (const float*)d_in[9];
    float* out = (float*)d_out;

    int N = in_sizes[0] / CC;
    int B = in_sizes[1];

    k_segsum<<<4096, 256>>>((const float4*)x, o, N, B);
    k_prep<<<1, 1024>>>(o, W2, b2, W1, b1, gam, bet, rmean, rvar, B);
    k_main<<<(N + 127) / 128, 256>>>((const float4*)x, o, out, N, B);
}

// round 12
// speedup vs baseline: 1.3740x; 1.0604x over previous
#include <cuda_runtime.h>
#include <cuda_fp16.h>
#include <cstdint>

#define CC 64
#define MAXB 16

// ---------------- device scratch (no allocations allowed) ----------------
__device__ float g_sums[MAXB * CC];                   // zeroed by k_prep after use (globals start zeroed)
__device__ __align__(16) float g_c[MAXB * CC];        // per-segment fused bias (BN folded)
__device__ __align__(16) uint32_t g_Wfrag[2048];      // B frags fp16: uint2 = {b0, b1} per (kt,n,lane)

__device__ __forceinline__ uint32_t smem_u32(const void* p) {
    uint32_t a;
    asm("{ .reg .u64 t; cvta.to.shared.u64 t, %1; cvt.u32.u64 %0, t; }" : "=r"(a) : "l"(p));
    return a;
}

// Veltkamp split at 13 bits: hi exactly fp16-representable, lo = exact residual.
__device__ __forceinline__ void vsplit(float v, float& hi, float& lo) {
    float t = __fmul_rn(v, 8193.0f);       // 2^13 + 1
    float d = __fsub_rn(t, v);
    hi = __fsub_rn(t, d);
    lo = __fsub_rn(v, hi);
}

// ---------------- pass 1: segment sums (float4, MLP=4, smem tree, few atomics) ----------------
// grid=1024: one wave at occ 8, block span divides equal segments exactly (no crossings),
// 4x fewer reduction tails than grid=4096.
__global__ void k_segsum(const float4* __restrict__ x4, const int* __restrict__ o,
                         int N, int Bseg) {
    __shared__ int so[MAXB];
    __shared__ float4 red[256];
    int t = threadIdx.x;
    if (t < Bseg) so[t] = o[t];
    __syncthreads();
    int c4 = t & 15, rg = t >> 4;
    int rpb = (N + gridDim.x - 1) / gridDim.x;
    int r0 = blockIdx.x * rpb;
    if (r0 >= N) return;
    int r1 = min(N, r0 + rpb);
    int s0 = 0; while (s0 < Bseg - 1 && r0 >= so[s0]) s0++;
    int s1 = s0; while (s1 < Bseg - 1 && (r1 - 1) >= so[s1]) s1++;
    if (s0 == s1) {
        float4 a0 = make_float4(0.f, 0.f, 0.f, 0.f);
        float4 a1 = make_float4(0.f, 0.f, 0.f, 0.f);
        float4 a2 = make_float4(0.f, 0.f, 0.f, 0.f);
        float4 a3 = make_float4(0.f, 0.f, 0.f, 0.f);
        int row = r0 + rg;
        for (; row + 48 < r1; row += 64) {
            float4 v0 = x4[(size_t)row * 16 + c4];
            float4 v1 = x4[(size_t)(row + 16) * 16 + c4];
            float4 v2 = x4[(size_t)(row + 32) * 16 + c4];
            float4 v3 = x4[(size_t)(row + 48) * 16 + c4];
            a0.x += v0.x; a0.y += v0.y; a0.z += v0.z; a0.w += v0.w;
            a1.x += v1.x; a1.y += v1.y; a1.z += v1.z; a1.w += v1.w;
            a2.x += v2.x; a2.y += v2.y; a2.z += v2.z; a2.w += v2.w;
            a3.x += v3.x; a3.y += v3.y; a3.z += v3.z; a3.w += v3.w;
        }
        for (; row < r1; row += 16) {
            float4 v = x4[(size_t)row * 16 + c4];
            a0.x += v.x; a0.y += v.y; a0.z += v.z; a0.w += v.w;
        }
        a0.x += a1.x + a2.x + a3.x; a0.y += a1.y + a2.y + a3.y;
        a0.z += a1.z + a2.z + a3.z; a0.w += a1.w + a2.w + a3.w;
        red[t] = a0;
        __syncthreads();
        #pragma unroll
        for (int s = 8; s >= 1; s >>= 1) {
            if (rg < s) {
                float4 b = red[t + 16 * s];
                float4 a = red[t];
                a.x += b.x; a.y += b.y; a.z += b.z; a.w += b.w;
                red[t] = a;
            }
            __syncthreads();
        }
        if (rg == 0) {
            float4 v = red[t];
            float* dst = &g_sums[s0 * CC + c4 * 4];
            atomicAdd(dst + 0, v.x); atomicAdd(dst + 1, v.y);
            atomicAdd(dst + 2, v.z); atomicAdd(dst + 3, v.w);
        }
    } else {
        int seg = s0;
        float4 a = make_float4(0.f, 0.f, 0.f, 0.f);
        for (int row = r0 + rg; row < r1; row += 16) {
            while (seg < Bseg - 1 && row >= so[seg]) {
                float* dst = &g_sums[seg * CC + c4 * 4];
                atomicAdd(dst + 0, a.x); atomicAdd(dst + 1, a.y);
                atomicAdd(dst + 2, a.z); atomicAdd(dst + 3, a.w);
                a = make_float4(0.f, 0.f, 0.f, 0.f);
                seg++;
            }
            float4 v = x4[(size_t)row * 16 + c4];
            a.x += v.x; a.y += v.y; a.z += v.z; a.w += v.w;
        }
        float* dst = &g_sums[seg * CC + c4 * 4];
        atomicAdd(dst + 0, a.x); atomicAdd(dst + 1, a.y);
        atomicAdd(dst + 2, a.z); atomicAdd(dst + 3, a.w);
    }
}

// ---------------- pass 2 (tiny): W1 staged in SMEM, MLP on pooled means, fold BN, B frags ----------------
__global__ void k_prep(const int* __restrict__ o, const float* __restrict__ W2,
                       const float* __restrict__ b2, const float* __restrict__ W1,
                       const float* __restrict__ b1, const float* __restrict__ gam,
                       const float* __restrict__ bet, const float* __restrict__ rmean,
                       const float* __restrict__ rvar, int Bseg) {
    __shared__ float sW1[8192];      // 32 KB: full W1 [128][64]
    __shared__ float mh[1024];       // mean, then h (Bseg*CC <= 1024)
    __shared__ float ss[CC], st[CC];
    int tid = threadIdx.x;

    // stage W1 with coalesced float4 (2 per thread, full MLP)
    {
        const float4* src = reinterpret_cast<const float4*>(W1);
        float4* dst = reinterpret_cast<float4*>(sW1);
        dst[tid] = src[tid];
        dst[tid + 1024] = src[tid + 1024];
    }
    if (tid < CC) {
        float sv = gam[tid] * rsqrtf(rvar[tid] + 1e-5f);
        ss[tid] = sv;
        st[tid] = bet[tid] - rmean[tid] * sv;
    }
    if (tid < Bseg * CC) {
        int b = tid >> 6;
        int cnt = o[b] - (b ? o[b - 1] : 0);
        mh[tid] = g_sums[tid] / (float)cnt;
        g_sums[tid] = 0.f;               // re-zero for next graph replay
    }
    __syncthreads();

    // h into registers (W2 via __ldg, fully unrolled independent loads)
    float hval = 0.f;
    if (tid < Bseg * CC) {
        int b = tid >> 6, j = tid & 63;
        float acc = b2[j];
        #pragma unroll
        for (int k = 0; k < CC; k++) acc = fmaf(mh[b * CC + k], __ldg(&W2[k * CC + j]), acc);
        hval = fmaxf(acc, 0.f);
    }
    // B frag image (fp16): word i = ((kt*8 + n)*32 + lane)*2 + bslot
    //   frag col f = lane>>2, column PERMUTED for stmatrix-natural staging:
    //     n_col = n*8 + (f>>1) + (f&1)*4
    //   k2 = kt*16 + (lane&3)*2 + bslot*8;  W'[k][n] = W1[k*CC+n]*ss[n]
    #pragma unroll
    for (int w = 0; w < 2; w++) {
        int i = tid + 1024 * w;
        int bslot = i & 1;
        int lane = (i >> 1) & 31;
        int grp = i >> 6;
        int n = grp & 7;
        int kt = grp >> 3;
        int f = lane >> 2;
        int n_col = n * 8 + (f >> 1) + ((f & 1) << 2);
        int k2 = kt * 16 + (lane & 3) * 2 + bslot * 8;
        float sv = ss[n_col];
        float w0 = sW1[k2 * CC + n_col] * sv;
        float w1v = sW1[(k2 + 1) * CC + n_col] * sv;
        __half2 hp = __floats2half2_rn(w0, w1v);
        g_Wfrag[i] = *reinterpret_cast<uint32_t*>(&hp);
    }
    __syncthreads();
    if (tid < Bseg * CC) mh[tid] = hval;
    __syncthreads();
    // per-segment fused bias: c = (h @ W1_bot + b1) * ss + st   (W1_bot from SMEM)
    if (tid < Bseg * CC) {
        int b = tid >> 6, j = tid & 63;
        float acc = b1[j];
        #pragma unroll
        for (int k = 0; k < CC; k++) acc = fmaf(mh[b * CC + k], sW1[(CC + k) * CC + j], acc);
        g_c[tid] = acc * ss[j] + st[j];
    }
}

// ---------------- MMA / ldmatrix / stmatrix helpers ----------------
__device__ __forceinline__ void mma16816h(float* c, const uint4& a, uint32_t b0, uint32_t b1) {
    asm volatile(
        "mma.sync.aligned.m16n8k16.row.col.f32.f16.f16.f32 "
        "{%0,%1,%2,%3}, {%4,%5,%6,%7}, {%8,%9}, {%0,%1,%2,%3};"
        : "+f"(c[0]), "+f"(c[1]), "+f"(c[2]), "+f"(c[3])
        : "r"(a.x), "r"(a.y), "r"(a.z), "r"(a.w), "r"(b0), "r"(b1));
}
__device__ __forceinline__ uint4 ldsm_x4(uint32_t addr) {
    uint4 r;
    asm volatile("ldmatrix.sync.aligned.m8n8.x4.shared.b16 {%0,%1,%2,%3}, [%4];"
        : "=r"(r.x), "=r"(r.y), "=r"(r.z), "=r"(r.w) : "r"(addr));
    return r;
}
__device__ __forceinline__ void stsm_x4(uint32_t addr, uint32_t r0, uint32_t r1,
                                        uint32_t r2, uint32_t r3) {
    asm volatile("stmatrix.sync.aligned.m8n8.x4.shared.b16 [%0], {%1,%2,%3,%4};"
        :: "r"(addr), "r"(r0), "r"(r1), "r"(r2), "r"(r3) : "memory");
}

// ---------------- pass 3: out = relu(x @ W' + c[seg]) via fp16 2-term A split ----------------
// A panels: fp16[128 rows][64 k], 128 B/row, SW128 swizzle. hi at 0, lo at 16384.
// After the MMA loop, A region is reused as fp32 output stage: 128 rows x 256 B,
// 16B chunk at (row, c16) stored at byte row*256 + ((c16*16) ^ ((row&7)<<4)).
struct __align__(1024) SmemM {
    unsigned char A[32768];
    uint2 Bimg[1024];           // 8 KB: {b0, b1} fp16 pairs per (kt,n,lane)
    unsigned char segb[128];
};

__global__ __launch_bounds__(256)
void k_main(const float4* __restrict__ x4, const int* __restrict__ o,
            float* __restrict__ out, int N, int Bseg) {
    __shared__ SmemM sm;
    int tid = threadIdx.x;
    int base = blockIdx.x * 128;

    // copy B frag image (coalesced, 8 KB)
    {
        const uint4* src = reinterpret_cast<const uint4*>(g_Wfrag);
        uint4* dst = reinterpret_cast<uint4*>(sm.Bimg);
        #pragma unroll
        for (int j = 0; j < 2; j++) dst[tid + 256 * j] = src[tid + 256 * j];
    }
    // per-row segment ids
    if (tid < 128) {
        int row = min(base + tid, N - 1);
        int s = 0;
        while (s < Bseg - 1 && row >= __ldg(&o[s])) s++;
        sm.segb[tid] = (unsigned char)s;
    }

    // load x coalesced, Veltkamp hi/lo split (FFMA pipe only), pack fp16, STS.64 x2
    #pragma unroll
    for (int j = 0; j < 8; j++) {
        int idx = tid + 256 * j;
        int row = idx >> 4, c4 = idx & 15;
        int grow = base + row;
        float4 v = make_float4(0.f, 0.f, 0.f, 0.f);
        if (grow < N) v = x4[(size_t)grow * 16 + c4];

        float hx, lx, hy, ly, hz, lz, hw_, lw_;
        vsplit(v.x, hx, lx); vsplit(v.y, hy, ly);
        vsplit(v.z, hz, lz); vsplit(v.w, hw_, lw_);
        __half2 h0 = __floats2half2_rn(hx, hy);   // exact: hi has <=11-bit mantissa
        __half2 h1 = __floats2half2_rn(hz, hw_);
        __half2 l0 = __floats2half2_rn(lx, ly);
        __half2 l1 = __floats2half2_rn(lz, lw_);

        uint32_t off = (uint32_t)(row * 128 + ((c4 * 8) ^ ((row & 7) << 4)));
        uint2 hw2 = make_uint2(*reinterpret_cast<uint32_t*>(&h0), *reinterpret_cast<uint32_t*>(&h1));
        uint2 lw2 = make_uint2(*reinterpret_cast<uint32_t*>(&l0), *reinterpret_cast<uint32_t*>(&l1));
        *reinterpret_cast<uint2*>(&sm.A[off])         = hw2;
        *reinterpret_cast<uint2*>(&sm.A[off + 16384]) = lw2;
    }
    __syncthreads();

    int lane = tid & 31, wid = tid >> 5;
    int wm = wid & 3;      // row group: rows wm*32 .. +31
    int wn = wid >> 2;     // col group: cols wn*32 .. +31

    int lm = lane >> 3, lr = lane & 7;
    uint32_t a_base = smem_u32(sm.A);
    uint32_t lane_row = (uint32_t)(wm * 32 + (lm & 1) * 8 + lr) * 128u;

    float acc[2][4][4];
    #pragma unroll
    for (int mb = 0; mb < 2; mb++)
        #pragma unroll
        for (int nt = 0; nt < 4; nt++)
            #pragma unroll
            for (int q = 0; q < 4; q++) acc[mb][nt][q] = 0.f;

    #pragma unroll
    for (int kt = 0; kt < 4; kt++) {
        uint32_t kcol = (uint32_t)((kt * 32 + (lm >> 1) * 16) ^ (lr << 4));
        uint4 ah[2], al[2];
        #pragma unroll
        for (int mb = 0; mb < 2; mb++) {
            uint32_t addr = a_base + lane_row + (uint32_t)(mb * 16 * 128) + kcol;
            ah[mb] = ldsm_x4(addr);
            al[mb] = ldsm_x4(addr + 16384);
        }
        #pragma unroll
        for (int nt = 0; nt < 4; nt++) {
            uint2 bv = sm.Bimg[(kt * 8 + wn * 4 + nt) * 32 + lane];
            #pragma unroll
            for (int mb = 0; mb < 2; mb++) {
                mma16816h(acc[mb][nt], ah[mb], bv.x, bv.y);   // hi * W
                mma16816h(acc[mb][nt], al[mb], bv.x, bv.y);   // lo * W
            }
        }
    }
    __syncthreads();   // all warps done reading A panels

    // stage accumulators via stmatrix.x4 (column-permuted B makes this row-natural)
    {
        int m = lane >> 3, rl8 = lane & 7;
        #pragma unroll
        for (int mb = 0; mb < 2; mb++) {
            int rrow = wm * 32 + mb * 16 + ((m & 1) << 3) + rl8;
            uint32_t rowb = a_base + (uint32_t)(rrow * 256);
            #pragma unroll
            for (int nt = 0; nt < 4; nt++) {
                int ci = wn * 8 + nt * 2 + (m >> 1);
                uint32_t addr = rowb + (uint32_t)((ci * 16) ^ (rl8 << 4));
                stsm_x4(addr,
                        __float_as_uint(acc[mb][nt][0]), __float_as_uint(acc[mb][nt][2]),
                        __float_as_uint(acc[mb][nt][1]), __float_as_uint(acc[mb][nt][3]));
            }
        }
    }
    __syncthreads();

    // read stage, add bias, relu, coalesced STG.128
    float4* out4 = reinterpret_cast<float4*>(out);
    #pragma unroll
    for (int j = 0; j < 8; j++) {
        int idx = tid + 256 * j;
        int row = idx >> 4, c4 = idx & 15;
        int grow = base + row;
        if (grow < N) {
            const float4 v = *reinterpret_cast<const float4*>(
                &sm.A[row * 256 + ((c4 * 16) ^ ((row & 7) << 4))]);
            int seg = sm.segb[row];
            float4 b = __ldg(reinterpret_cast<const float4*>(&g_c[seg * CC + c4 * 4]));
            float4 r;
            r.x = fmaxf(v.x + b.x, 0.f);
            r.y = fmaxf(v.y + b.y, 0.f);
            r.z = fmaxf(v.z + b.z, 0.f);
            r.w = fmaxf(v.w + b.w, 0.f);
            out4[(size_t)grow * 16 + c4] = r;
        }
    }
}

extern "C" void kernel_launch(void* const* d_in, const int* in_sizes, int n_in,
                              void* d_out, int out_size) {
    const float* x     = (const float*)d_in[0];
    const int*   o     = (const int*)  d_in[1];
    const float* W2    = (const float*)d_in[2];
    const float* b2    = (const float*)d_in[3];
    const float* W1    = (const float*)d_in[4];
    const float* b1    = (const float*)d_in[5];
    const float* gam   = (const float*)d_in[6];
    const float* bet   = (const float*)d_in[7];
    const float* rmean = (const float*)d_in[8];
    const float* rvar  = (const float*)d_in[9];
    float* out = (float*)d_out;

    int N = in_sizes[0] / CC;
    int B = in_sizes[1];

    k_segsum<<<1024, 256>>>((const float4*)x, o, N, B);
    k_prep<<<1, 1024>>>(o, W2, b2, W1, b1, gam, bet, rmean, rvar, B);
    k_main<<<(N + 127) / 128, 256>>>((const float4*)x, o, out, N, B);
}

// round 13
// speedup vs baseline: 1.5246x; 1.1096x over previous
#include <cuda_runtime.h>
#include <cuda_fp16.h>
#include <cstdint>

#define CC 64
#define MAXB 16

// ---------------- device scratch (no allocations allowed) ----------------
__device__ float g_sums[MAXB * CC];                   // zeroed by k_prep after use (globals start zeroed)
__device__ __align__(16) float g_c[MAXB * CC];        // per-segment fused bias (BN folded)
__device__ __align__(16) uint32_t g_Wfrag[2048];      // B frags fp16: uint2 = {b0, b1} per (kt,n,lane)

__device__ __forceinline__ uint32_t smem_u32(const void* p) {
    uint32_t a;
    asm("{ .reg .u64 t; cvta.to.shared.u64 t, %1; cvt.u32.u64 %0, t; }" : "=r"(a) : "l"(p));
    return a;
}

// ---------------- pass 1: segment sums (float4, MLP=4, smem tree, few atomics) ----------------
__global__ void k_segsum(const float4* __restrict__ x4, const int* __restrict__ o,
                         int N, int Bseg) {
    __shared__ int so[MAXB];
    __shared__ float4 red[256];
    int t = threadIdx.x;
    if (t < Bseg) so[t] = o[t];
    __syncthreads();
    int c4 = t & 15, rg = t >> 4;
    int rpb = (N + gridDim.x - 1) / gridDim.x;
    int r0 = blockIdx.x * rpb;
    if (r0 >= N) return;
    int r1 = min(N, r0 + rpb);
    int s0 = 0; while (s0 < Bseg - 1 && r0 >= so[s0]) s0++;
    int s1 = s0; while (s1 < Bseg - 1 && (r1 - 1) >= so[s1]) s1++;
    if (s0 == s1) {
        float4 a0 = make_float4(0.f, 0.f, 0.f, 0.f);
        float4 a1 = make_float4(0.f, 0.f, 0.f, 0.f);
        float4 a2 = make_float4(0.f, 0.f, 0.f, 0.f);
        float4 a3 = make_float4(0.f, 0.f, 0.f, 0.f);
        int row = r0 + rg;
        for (; row + 48 < r1; row += 64) {
            float4 v0 = x4[(size_t)row * 16 + c4];
            float4 v1 = x4[(size_t)(row + 16) * 16 + c4];
            float4 v2 = x4[(size_t)(row + 32) * 16 + c4];
            float4 v3 = x4[(size_t)(row + 48) * 16 + c4];
            a0.x += v0.x; a0.y += v0.y; a0.z += v0.z; a0.w += v0.w;
            a1.x += v1.x; a1.y += v1.y; a1.z += v1.z; a1.w += v1.w;
            a2.x += v2.x; a2.y += v2.y; a2.z += v2.z; a2.w += v2.w;
            a3.x += v3.x; a3.y += v3.y; a3.z += v3.z; a3.w += v3.w;
        }
        for (; row < r1; row += 16) {
            float4 v = x4[(size_t)row * 16 + c4];
            a0.x += v.x; a0.y += v.y; a0.z += v.z; a0.w += v.w;
        }
        a0.x += a1.x + a2.x + a3.x; a0.y += a1.y + a2.y + a3.y;
        a0.z += a1.z + a2.z + a3.z; a0.w += a1.w + a2.w + a3.w;
        red[t] = a0;
        __syncthreads();
        #pragma unroll
        for (int s = 8; s >= 1; s >>= 1) {
            if (rg < s) {
                float4 b = red[t + 16 * s];
                float4 a = red[t];
                a.x += b.x; a.y += b.y; a.z += b.z; a.w += b.w;
                red[t] = a;
            }
            __syncthreads();
        }
        if (rg == 0) {
            float4 v = red[t];
            float* dst = &g_sums[s0 * CC + c4 * 4];
            atomicAdd(dst + 0, v.x); atomicAdd(dst + 1, v.y);
            atomicAdd(dst + 2, v.z); atomicAdd(dst + 3, v.w);
        }
    } else {
        int seg = s0;
        float4 a = make_float4(0.f, 0.f, 0.f, 0.f);
        for (int row = r0 + rg; row < r1; row += 16) {
            while (seg < Bseg - 1 && row >= so[seg]) {
                float* dst = &g_sums[seg * CC + c4 * 4];
                atomicAdd(dst + 0, a.x); atomicAdd(dst + 1, a.y);
                atomicAdd(dst + 2, a.z); atomicAdd(dst + 3, a.w);
                a = make_float4(0.f, 0.f, 0.f, 0.f);
                seg++;
            }
            float4 v = x4[(size_t)row * 16 + c4];
            a.x += v.x; a.y += v.y; a.z += v.z; a.w += v.w;
        }
        float* dst = &g_sums[seg * CC + c4 * 4];
        atomicAdd(dst + 0, a.x); atomicAdd(dst + 1, a.y);
        atomicAdd(dst + 2, a.z); atomicAdd(dst + 3, a.w);
    }
}

// ---------------- pass 2 (tiny): W1 staged in SMEM, MLP on pooled means, fold BN, B frags ----------------
__global__ void k_prep(const int* __restrict__ o, const float* __restrict__ W2,
                       const float* __restrict__ b2, const float* __restrict__ W1,
                       const float* __restrict__ b1, const float* __restrict__ gam,
                       const float* __restrict__ bet, const float* __restrict__ rmean,
                       const float* __restrict__ rvar, int Bseg) {
    __shared__ float sW1[8192];      // 32 KB: full W1 [128][64]
    __shared__ float mh[1024];       // mean, then h (Bseg*CC <= 1024)
    __shared__ float ss[CC], st[CC];
    int tid = threadIdx.x;

    {
        const float4* src = reinterpret_cast<const float4*>(W1);
        float4* dst = reinterpret_cast<float4*>(sW1);
        dst[tid] = src[tid];
        dst[tid + 1024] = src[tid + 1024];
    }
    if (tid < CC) {
        float sv = gam[tid] * rsqrtf(rvar[tid] + 1e-5f);
        ss[tid] = sv;
        st[tid] = bet[tid] - rmean[tid] * sv;
    }
    if (tid < Bseg * CC) {
        int b = tid >> 6;
        int cnt = o[b] - (b ? o[b - 1] : 0);
        mh[tid] = g_sums[tid] / (float)cnt;
        g_sums[tid] = 0.f;               // re-zero for next graph replay
    }
    __syncthreads();

    float hval = 0.f;
    if (tid < Bseg * CC) {
        int b = tid >> 6, j = tid & 63;
        float acc = b2[j];
        #pragma unroll
        for (int k = 0; k < CC; k++) acc = fmaf(mh[b * CC + k], __ldg(&W2[k * CC + j]), acc);
        hval = fmaxf(acc, 0.f);
    }
    // B frag image (fp16): word i = ((kt*8 + n)*32 + lane)*2 + bslot
    //   frag col f = lane>>2, column PERMUTED for stmatrix-natural staging:
    //     n_col = n*8 + (f>>1) + (f&1)*4
    //   k2 = kt*16 + (lane&3)*2 + bslot*8;  W'[k][n] = W1[k*CC+n]*ss[n]
    #pragma unroll
    for (int w = 0; w < 2; w++) {
        int i = tid + 1024 * w;
        int bslot = i & 1;
        int lane = (i >> 1) & 31;
        int grp = i >> 6;
        int n = grp & 7;
        int kt = grp >> 3;
        int f = lane >> 2;
        int n_col = n * 8 + (f >> 1) + ((f & 1) << 2);
        int k2 = kt * 16 + (lane & 3) * 2 + bslot * 8;
        float sv = ss[n_col];
        float w0 = sW1[k2 * CC + n_col] * sv;
        float w1v = sW1[(k2 + 1) * CC + n_col] * sv;
        __half2 hp = __floats2half2_rn(w0, w1v);
        g_Wfrag[i] = *reinterpret_cast<uint32_t*>(&hp);
    }
    __syncthreads();
    if (tid < Bseg * CC) mh[tid] = hval;
    __syncthreads();
    if (tid < Bseg * CC) {
        int b = tid >> 6, j = tid & 63;
        float acc = b1[j];
        #pragma unroll
        for (int k = 0; k < CC; k++) acc = fmaf(mh[b * CC + k], sW1[(CC + k) * CC + j], acc);
        g_c[tid] = acc * ss[j] + st[j];
    }
}

// ---------------- MMA / ldmatrix / stmatrix helpers ----------------
__device__ __forceinline__ void mma16816h(float* c, const uint4& a, uint32_t b0, uint32_t b1) {
    asm volatile(
        "mma.sync.aligned.m16n8k16.row.col.f32.f16.f16.f32 "
        "{%0,%1,%2,%3}, {%4,%5,%6,%7}, {%8,%9}, {%0,%1,%2,%3};"
        : "+f"(c[0]), "+f"(c[1]), "+f"(c[2]), "+f"(c[3])
        : "r"(a.x), "r"(a.y), "r"(a.z), "r"(a.w), "r"(b0), "r"(b1));
}
__device__ __forceinline__ uint4 ldsm_x4(uint32_t addr) {
    uint4 r;
    asm volatile("ldmatrix.sync.aligned.m8n8.x4.shared.b16 {%0,%1,%2,%3}, [%4];"
        : "=r"(r.x), "=r"(r.y), "=r"(r.z), "=r"(r.w) : "r"(addr));
    return r;
}
__device__ __forceinline__ void stsm_x4(uint32_t addr, uint32_t r0, uint32_t r1,
                                        uint32_t r2, uint32_t r3) {
    asm volatile("stmatrix.sync.aligned.m8n8.x4.shared.b16 [%0], {%1,%2,%3,%4};"
        :: "r"(addr), "r"(r0), "r"(r1), "r"(r2), "r"(r3) : "memory");
}

// ---------------- pass 3: out = relu(x @ W' + c[seg]) via single-term fp16 HMMA ----------------
// A panel: fp16[128 rows][64 k], 128 B/row, SW128 swizzle, in buf[0..16384).
// After the MMA loop, buf is reused as fp32 output stage: 128 rows x 256 B,
// 16B chunk at (row, c16) at byte row*256 + ((c16*16) ^ ((row&7)<<4)).
struct __align__(1024) SmemM {
    unsigned char buf[32768];   // A panel (16 KB) -> fp32 stage (32 KB)
    uint2 Bimg[1024];           // 8 KB: {b0, b1} fp16 pairs per (kt,n,lane)
    float cbias[MAXB * CC];     // 4 KB: bias table
    unsigned char segb[128];
};

__global__ __launch_bounds__(256)
void k_main(const float4* __restrict__ x4, const int* __restrict__ o,
            float* __restrict__ out, int N, int Bseg) {
    __shared__ SmemM sm;
    int tid = threadIdx.x;
    int base = blockIdx.x * 128;

    // copy B frag image (8 KB) and bias table (4 KB), coalesced
    {
        const uint4* src = reinterpret_cast<const uint4*>(g_Wfrag);
        uint4* dst = reinterpret_cast<uint4*>(sm.Bimg);
        #pragma unroll
        for (int j = 0; j < 2; j++) dst[tid + 256 * j] = src[tid + 256 * j];
        reinterpret_cast<float4*>(sm.cbias)[tid] =
            reinterpret_cast<const float4*>(g_c)[tid];
    }
    // per-row segment ids
    if (tid < 128) {
        int row = min(base + tid, N - 1);
        int s = 0;
        while (s < Bseg - 1 && row >= __ldg(&o[s])) s++;
        sm.segb[tid] = (unsigned char)s;
    }

    // load x coalesced, round to fp16, STS.64 swizzled
    #pragma unroll
    for (int j = 0; j < 8; j++) {
        int idx = tid + 256 * j;
        int row = idx >> 4, c4 = idx & 15;
        int grow = base + row;
        float4 v = make_float4(0.f, 0.f, 0.f, 0.f);
        if (grow < N) v = x4[(size_t)grow * 16 + c4];

        __half2 h0 = __floats2half2_rn(v.x, v.y);
        __half2 h1 = __floats2half2_rn(v.z, v.w);
        uint32_t off = (uint32_t)(row * 128 + ((c4 * 8) ^ ((row & 7) << 4)));
        *reinterpret_cast<uint2*>(&sm.buf[off]) =
            make_uint2(*reinterpret_cast<uint32_t*>(&h0), *reinterpret_cast<uint32_t*>(&h1));
    }
    __syncthreads();

    int lane = tid & 31, wid = tid >> 5;
    int wm = wid & 3;      // row group: rows wm*32 .. +31
    int wn = wid >> 2;     // col group: cols wn*32 .. +31

    int lm = lane >> 3, lr = lane & 7;
    uint32_t a_base = smem_u32(sm.buf);
    uint32_t lane_row = (uint32_t)(wm * 32 + (lm & 1) * 8 + lr) * 128u;

    float acc[2][4][4];
    #pragma unroll
    for (int mb = 0; mb < 2; mb++)
        #pragma unroll
        for (int nt = 0; nt < 4; nt++)
            #pragma unroll
            for (int q = 0; q < 4; q++) acc[mb][nt][q] = 0.f;

    #pragma unroll
    for (int kt = 0; kt < 4; kt++) {
        uint32_t kcol = (uint32_t)((kt * 32 + (lm >> 1) * 16) ^ (lr << 4));
        uint4 ah[2];
        #pragma unroll
        for (int mb = 0; mb < 2; mb++)
            ah[mb] = ldsm_x4(a_base + lane_row + (uint32_t)(mb * 16 * 128) + kcol);
        #pragma unroll
        for (int nt = 0; nt < 4; nt++) {
            uint2 bv = sm.Bimg[(kt * 8 + wn * 4 + nt) * 32 + lane];
            #pragma unroll
            for (int mb = 0; mb < 2; mb++)
                mma16816h(acc[mb][nt], ah[mb], bv.x, bv.y);
        }
    }
    __syncthreads();   // all warps done reading A panel

    // stage accumulators via stmatrix.x4 (column-permuted B makes this row-natural)
    {
        int m = lane >> 3, rl8 = lane & 7;
        #pragma unroll
        for (int mb = 0; mb < 2; mb++) {
            int rrow = wm * 32 + mb * 16 + ((m & 1) << 3) + rl8;
            uint32_t rowb = a_base + (uint32_t)(rrow * 256);
            #pragma unroll
            for (int nt = 0; nt < 4; nt++) {
                int ci = wn * 8 + nt * 2 + (m >> 1);
                uint32_t addr = rowb + (uint32_t)((ci * 16) ^ (rl8 << 4));
                stsm_x4(addr,
                        __float_as_uint(acc[mb][nt][0]), __float_as_uint(acc[mb][nt][2]),
                        __float_as_uint(acc[mb][nt][1]), __float_as_uint(acc[mb][nt][3]));
            }
        }
    }
    __syncthreads();

    // read stage, add bias (SMEM), relu, coalesced STG.128
    float4* out4 = reinterpret_cast<float4*>(out);
    #pragma unroll
    for (int j = 0; j < 8; j++) {
        int idx = tid + 256 * j;
        int row = idx >> 4, c4 = idx & 15;
        int grow = base + row;
        if (grow < N) {
            const float4 v = *reinterpret_cast<const float4*>(
                &sm.buf[row * 256 + ((c4 * 16) ^ ((row & 7) << 4))]);
            int seg = sm.segb[row];
            const float4 b = *reinterpret_cast<const float4*>(&sm.cbias[seg * CC + c4 * 4]);
            float4 r;
            r.x = fmaxf(v.x + b.x, 0.f);
            r.y = fmaxf(v.y + b.y, 0.f);
            r.z = fmaxf(v.z + b.z, 0.f);
            r.w = fmaxf(v.w + b.w, 0.f);
            out4[(size_t)grow * 16 + c4] = r;
        }
    }
}

extern "C" void kernel_launch(void* const* d_in, const int* in_sizes, int n_in,
                              void* d_out, int out_size) {
    const float* x     = (const float*)d_in[0];
    const int*   o     = (const int*)  d_in[1];
    const float* W2    = (const float*)d_in[2];
    const float* b2    = (const float*)d_in[3];
    const float* W1    = (const float*)d_in[4];
    const float* b1    = (const float*)d_in[5];
    const float* gam   = (const float*)d_in[6];
    const float* bet   = (const float*)d_in[7];
    const float* rmean = (const float*)d_in[8];
    const float* rvar  = (const float*)d_in[9];
    float* out = (float*)d_out;

    int N = in_sizes[0] / CC;
    int B = in_sizes[1];

    k_segsum<<<1024, 256>>>((const float4*)x, o, N, B);
    k_prep<<<1, 1024>>>(o, W2, b2, W1, b1, gam, bet, rmean, rvar, B);
    k_main<<<(N + 127) / 128, 256>>>((const float4*)x, o, out, N, B);
}